// round 10
// baseline (speedup 1.0000x reference)
#include <cuda_runtime.h>

#define N_NODES 100000
#define N_EDGES 3200000
#define C_DIM   256
#define NEG_SLOPE 0.2f

// Scratch (allocation-free): node score arrays + softmax denominator.
__device__ float g_s_src[N_NODES];
__device__ float g_s_dst[N_NODES];
__device__ float g_denom[N_NODES];

// ---------------------------------------------------------------------------
// Kernel 1: per-node scores s_src = x·att[:C], s_dst = x·att[C:], zero denom.
// R10 experiment: FOUR nodes per warp — 8 front-batched LDG.128 (MLP 8),
// 8 interleaved reduce chains, single coalesced float4 store per array.
// N_NODES % 4 == 0 so pairing is exact. 25000 warps = 3125 blocks.
// ---------------------------------------------------------------------------
__global__ void __launch_bounds__(256)
node_scores_kernel(const float* __restrict__ x, const float* __restrict__ att) {
    const int gtid  = blockIdx.x * blockDim.x + threadIdx.x;
    const int warp  = gtid >> 5;            // 0 .. 24999
    const int lane  = threadIdx.x & 31;
    const int nodeA = warp * 4;
    if (nodeA >= N_NODES) return;

    const float4* a0 = reinterpret_cast<const float4*>(att);          // att[:C]
    const float4* a1 = reinterpret_cast<const float4*>(att + C_DIM);  // att[C:]

    // 4 contiguous x rows: 8 independent 16B loads issued up-front.
    const float4* xr = reinterpret_cast<const float4*>(x + (size_t)nodeA * C_DIM);
    float4 xa0 = xr[lane];        float4 xa1 = xr[lane + 32];
    float4 xb0 = xr[lane + 64];   float4 xb1 = xr[lane + 96];
    float4 xc0 = xr[lane + 128];  float4 xc1 = xr[lane + 160];
    float4 xd0 = xr[lane + 192];  float4 xd1 = xr[lane + 224];

    float4 av0 = a0[lane],      bv0 = a1[lane];       // L1/L2-resident (2KB)
    float4 av1 = a0[lane + 32], bv1 = a1[lane + 32];

    float s0a = xa0.x*av0.x + xa0.y*av0.y + xa0.z*av0.z + xa0.w*av0.w
              + xa1.x*av1.x + xa1.y*av1.y + xa1.z*av1.z + xa1.w*av1.w;
    float s1a = xa0.x*bv0.x + xa0.y*bv0.y + xa0.z*bv0.z + xa0.w*bv0.w
              + xa1.x*bv1.x + xa1.y*bv1.y + xa1.z*bv1.z + xa1.w*bv1.w;
    float s0b = xb0.x*av0.x + xb0.y*av0.y + xb0.z*av0.z + xb0.w*av0.w
              + xb1.x*av1.x + xb1.y*av1.y + xb1.z*av1.z + xb1.w*av1.w;
    float s1b = xb0.x*bv0.x + xb0.y*bv0.y + xb0.z*bv0.z + xb0.w*bv0.w
              + xb1.x*bv1.x + xb1.y*bv1.y + xb1.z*bv1.z + xb1.w*bv1.w;
    float s0c = xc0.x*av0.x + xc0.y*av0.y + xc0.z*av0.z + xc0.w*av0.w
              + xc1.x*av1.x + xc1.y*av1.y + xc1.z*av1.z + xc1.w*av1.w;
    float s1c = xc0.x*bv0.x + xc0.y*bv0.y + xc0.z*bv0.z + xc0.w*bv0.w
              + xc1.x*bv1.x + xc1.y*bv1.y + xc1.z*bv1.z + xc1.w*bv1.w;
    float s0d = xd0.x*av0.x + xd0.y*av0.y + xd0.z*av0.z + xd0.w*av0.w
              + xd1.x*av1.x + xd1.y*av1.y + xd1.z*av1.z + xd1.w*av1.w;
    float s1d = xd0.x*bv0.x + xd0.y*bv0.y + xd0.z*bv0.z + xd0.w*bv0.w
              + xd1.x*bv1.x + xd1.y*bv1.y + xd1.z*bv1.z + xd1.w*bv1.w;

#pragma unroll
    for (int off = 16; off; off >>= 1) {   // 8 independent reduce chains
        s0a += __shfl_down_sync(0xffffffffu, s0a, off);
        s1a += __shfl_down_sync(0xffffffffu, s1a, off);
        s0b += __shfl_down_sync(0xffffffffu, s0b, off);
        s1b += __shfl_down_sync(0xffffffffu, s1b, off);
        s0c += __shfl_down_sync(0xffffffffu, s0c, off);
        s1c += __shfl_down_sync(0xffffffffu, s1c, off);
        s0d += __shfl_down_sync(0xffffffffu, s0d, off);
        s1d += __shfl_down_sync(0xffffffffu, s1d, off);
    }
    if (lane == 0) {   // nodeA % 4 == 0 -> 16B-aligned float4 stores
        *reinterpret_cast<float4*>(&g_s_src[nodeA]) = make_float4(s0a, s0b, s0c, s0d);
        *reinterpret_cast<float4*>(&g_s_dst[nodeA]) = make_float4(s1a, s1b, s1c, s1d);
        *reinterpret_cast<float4*>(&g_denom[nodeA]) = make_float4(0.f, 0.f, 0.f, 0.f);
    }
}

// ---------------------------------------------------------------------------
// Kernel 2 (FROZEN at measured-best R7 config): per-edge
// e = exp(leaky_relu(s_src[row] + s_dst[col])). Max-shift dropped
// (mathematically identical; |a|<=~8, fp32-safe). 4 edges/thread, 3125
// blocks. row default-cached (stays L2-resident for kernel 3), col streamed.
// ---------------------------------------------------------------------------
__global__ void __launch_bounds__(256)
edge_exp_kernel(const int* __restrict__ row,
                const int* __restrict__ col,
                float* __restrict__ out) {
    int i = blockIdx.x * blockDim.x + threadIdx.x;   // quad index
    if (i * 4 >= N_EDGES) return;

    int4 r4 = reinterpret_cast<const int4*>(row)[i];            // keep in L2
    int4 c4 = __ldcs(&reinterpret_cast<const int4*>(col)[i]);   // read-once

    // 8 independent scattered gathers in flight
    float ss0 = g_s_src[r4.x], ss1 = g_s_src[r4.y];
    float ss2 = g_s_src[r4.z], ss3 = g_s_src[r4.w];
    float sd0 = g_s_dst[c4.x], sd1 = g_s_dst[c4.y];
    float sd2 = g_s_dst[c4.z], sd3 = g_s_dst[c4.w];

    float a0 = ss0 + sd0, a1 = ss1 + sd1, a2 = ss2 + sd2, a3 = ss3 + sd3;
    a0 = a0 > 0.f ? a0 : NEG_SLOPE * a0;
    a1 = a1 > 0.f ? a1 : NEG_SLOPE * a1;
    a2 = a2 > 0.f ? a2 : NEG_SLOPE * a2;
    a3 = a3 > 0.f ? a3 : NEG_SLOPE * a3;
    float e0 = __expf(a0), e1 = __expf(a1), e2 = __expf(a2), e3 = __expf(a3);

    reinterpret_cast<float4*>(out)[i] = make_float4(e0, e1, e2, e3);

    atomicAdd(&g_denom[r4.x], e0);
    atomicAdd(&g_denom[r4.y], e1);
    atomicAdd(&g_denom[r4.z], e2);
    atomicAdd(&g_denom[r4.w], e3);
}

// ---------------------------------------------------------------------------
// Kernel 3 (FROZEN at measured-best): out[e] = e / denom[row[e]].
// 2 edges/thread, 6250 blocks (U-shape optimum: 8/t:18.3, 4/t:15.9,
// 2/t:14.5, 1/t:19). row + out hit L2. __fdividef (2^-21, tol 1e-3).
// ---------------------------------------------------------------------------
__global__ void __launch_bounds__(256)
normalize_kernel(const int* __restrict__ row, float* __restrict__ out) {
    int i = blockIdx.x * blockDim.x + threadIdx.x;   // pair index
    if (i * 2 >= N_EDGES) return;

    int2 r2 = reinterpret_cast<const int2*>(row)[i];   // L2 hit expected

    float d0 = g_denom[r2.x];
    float d1 = g_denom[r2.y];

    float2 v = reinterpret_cast<float2*>(out)[i];
    v.x = __fdividef(v.x, d0);
    v.y = __fdividef(v.y, d1);
    reinterpret_cast<float2*>(out)[i] = v;
}

// ---------------------------------------------------------------------------
extern "C" void kernel_launch(void* const* d_in, const int* in_sizes, int n_in,
                              void* d_out, int out_size) {
    const float* x    = (const float*)d_in[0];   // (N, C) f32
    const float* att  = (const float*)d_in[1];   // (2C, 1) f32
    const int*   edge = (const int*)d_in[2];     // (2, E) int32
    float*       out  = (float*)d_out;           // (1, E) f32

    const int* row = edge;             // edge_index[0]
    const int* col = edge + N_EDGES;   // edge_index[1]

    {   // one-shot, 4 nodes per warp: 25000 warps = 3125 blocks
        int threads = 256;
        int blocks  = (N_NODES / 4 * 32) / threads;   // 3125
        node_scores_kernel<<<blocks, threads>>>(x, att);
    }
    {
        int threads = 256;
        int blocks = (N_EDGES / 4 + threads - 1) / threads;   // 3125
        edge_exp_kernel<<<blocks, threads>>>(row, col, out);
    }
    {
        int threads = 256;
        int blocks = (N_EDGES / 2 + threads - 1) / threads;   // 6250
        normalize_kernel<<<blocks, threads>>>(row, out);
    }
}

// round 11
// speedup vs baseline: 1.0434x; 1.0434x over previous
#include <cuda_runtime.h>

#define N_NODES 100000
#define N_EDGES 3200000
#define C_DIM   256
#define NEG_SLOPE 0.2f

// Scratch (allocation-free): node score arrays + softmax denominator.
__device__ float g_s_src[N_NODES];
__device__ float g_s_dst[N_NODES];
__device__ float g_denom[N_NODES];

// ---------------------------------------------------------------------------
// Kernel 1 (FROZEN at measured-best R7 config, ~20.0us @ 66% DRAM ceiling):
// per-node scores s_src = x·att[:C], s_dst = x·att[C:], zero denom.
// One-shot, 2 nodes/warp, 4 front-batched LDG.128, float2 stores.
// ---------------------------------------------------------------------------
__global__ void __launch_bounds__(256)
node_scores_kernel(const float* __restrict__ x, const float* __restrict__ att) {
    const int gtid  = blockIdx.x * blockDim.x + threadIdx.x;
    const int warp  = gtid >> 5;            // 0 .. 49999
    const int lane  = threadIdx.x & 31;
    const int nodeA = warp * 2;
    if (nodeA >= N_NODES) return;

    const float4* a0 = reinterpret_cast<const float4*>(att);          // att[:C]
    const float4* a1 = reinterpret_cast<const float4*>(att + C_DIM);  // att[C:]

    const float4* xr = reinterpret_cast<const float4*>(x + (size_t)nodeA * C_DIM);
    float4 xa0 = xr[lane];
    float4 xa1 = xr[lane + 32];
    float4 xb0 = xr[lane + 64];
    float4 xb1 = xr[lane + 96];

    float4 av0 = a0[lane],      bv0 = a1[lane];       // L1/L2-resident (2KB)
    float4 av1 = a0[lane + 32], bv1 = a1[lane + 32];

    float s0a = xa0.x*av0.x + xa0.y*av0.y + xa0.z*av0.z + xa0.w*av0.w
              + xa1.x*av1.x + xa1.y*av1.y + xa1.z*av1.z + xa1.w*av1.w;
    float s1a = xa0.x*bv0.x + xa0.y*bv0.y + xa0.z*bv0.z + xa0.w*bv0.w
              + xa1.x*bv1.x + xa1.y*bv1.y + xa1.z*bv1.z + xa1.w*bv1.w;
    float s0b = xb0.x*av0.x + xb0.y*av0.y + xb0.z*av0.z + xb0.w*av0.w
              + xb1.x*av1.x + xb1.y*av1.y + xb1.z*av1.z + xb1.w*av1.w;
    float s1b = xb0.x*bv0.x + xb0.y*bv0.y + xb0.z*bv0.z + xb0.w*bv0.w
              + xb1.x*bv1.x + xb1.y*bv1.y + xb1.z*bv1.z + xb1.w*bv1.w;

#pragma unroll
    for (int off = 16; off; off >>= 1) {   // 4 independent reduce chains
        s0a += __shfl_down_sync(0xffffffffu, s0a, off);
        s1a += __shfl_down_sync(0xffffffffu, s1a, off);
        s0b += __shfl_down_sync(0xffffffffu, s0b, off);
        s1b += __shfl_down_sync(0xffffffffu, s1b, off);
    }
    if (lane == 0) {   // coalesced pair stores (nodeA even -> 8B aligned)
        *reinterpret_cast<float2*>(&g_s_src[nodeA]) = make_float2(s0a, s0b);
        *reinterpret_cast<float2*>(&g_s_dst[nodeA]) = make_float2(s1a, s1b);
        *reinterpret_cast<float2*>(&g_denom[nodeA]) = make_float2(0.f, 0.f);
    }
}

// ---------------------------------------------------------------------------
// Kernel 2 (config FROZEN: 4 edges/thread, 3125 blocks). PDL: row/col index
// loads are issued BEFORE cudaGridDependencySynchronize() so they overlap
// node_scores' drain; s-table gathers / out store / denom RED come after.
// Max-shift dropped (mathematically identical; |a|<=~8, fp32-safe).
// ---------------------------------------------------------------------------
__global__ void __launch_bounds__(256)
edge_exp_kernel(const int* __restrict__ row,
                const int* __restrict__ col,
                float* __restrict__ out) {
    int i = blockIdx.x * blockDim.x + threadIdx.x;   // quad index
    if (i * 4 >= N_EDGES) {
        cudaGridDependencySynchronize();
        return;
    }

    // Independent of node_scores: issue before the dependency sync.
    int4 r4 = reinterpret_cast<const int4*>(row)[i];            // keep in L2
    int4 c4 = __ldcs(&reinterpret_cast<const int4*>(col)[i]);   // read-once

    cudaGridDependencySynchronize();   // s tables + denom zero now visible

    // 8 independent scattered gathers in flight
    float ss0 = g_s_src[r4.x], ss1 = g_s_src[r4.y];
    float ss2 = g_s_src[r4.z], ss3 = g_s_src[r4.w];
    float sd0 = g_s_dst[c4.x], sd1 = g_s_dst[c4.y];
    float sd2 = g_s_dst[c4.z], sd3 = g_s_dst[c4.w];

    float a0 = ss0 + sd0, a1 = ss1 + sd1, a2 = ss2 + sd2, a3 = ss3 + sd3;
    a0 = a0 > 0.f ? a0 : NEG_SLOPE * a0;
    a1 = a1 > 0.f ? a1 : NEG_SLOPE * a1;
    a2 = a2 > 0.f ? a2 : NEG_SLOPE * a2;
    a3 = a3 > 0.f ? a3 : NEG_SLOPE * a3;
    float e0 = __expf(a0), e1 = __expf(a1), e2 = __expf(a2), e3 = __expf(a3);

    reinterpret_cast<float4*>(out)[i] = make_float4(e0, e1, e2, e3);

    atomicAdd(&g_denom[r4.x], e0);
    atomicAdd(&g_denom[r4.y], e1);
    atomicAdd(&g_denom[r4.z], e2);
    atomicAdd(&g_denom[r4.w], e3);
}

// ---------------------------------------------------------------------------
// Kernel 3 (config FROZEN: 2 edges/thread, 6250 blocks). PDL: row loads
// pre-sync (independent of edge_exp); out/denom reads post-sync.
// __fdividef (2^-21, tol 1e-3).
// ---------------------------------------------------------------------------
__global__ void __launch_bounds__(256)
normalize_kernel(const int* __restrict__ row, float* __restrict__ out) {
    int i = blockIdx.x * blockDim.x + threadIdx.x;   // pair index
    if (i * 2 >= N_EDGES) {
        cudaGridDependencySynchronize();
        return;
    }

    int2 r2 = reinterpret_cast<const int2*>(row)[i];   // pre-sync, L2 hit

    cudaGridDependencySynchronize();   // e values + denom now complete

    float d0 = g_denom[r2.x];
    float d1 = g_denom[r2.y];

    float2 v = reinterpret_cast<float2*>(out)[i];
    v.x = __fdividef(v.x, d0);
    v.y = __fdividef(v.y, d1);
    reinterpret_cast<float2*>(out)[i] = v;
}

// ---------------------------------------------------------------------------
extern "C" void kernel_launch(void* const* d_in, const int* in_sizes, int n_in,
                              void* d_out, int out_size) {
    const float* x    = (const float*)d_in[0];   // (N, C) f32
    const float* att  = (const float*)d_in[1];   // (2C, 1) f32
    const int*   edge = (const int*)d_in[2];     // (2, E) int32
    float*       out  = (float*)d_out;           // (1, E) f32

    const int* row = edge;             // edge_index[0]
    const int* col = edge + N_EDGES;   // edge_index[1]

    {   // one-shot, 2 nodes per warp: 50000 warps = 6250 blocks
        node_scores_kernel<<<6250, 256>>>(x, att);
    }

    // PDL attribute for the two dependent launches
    cudaLaunchAttribute pdl_attr;
    pdl_attr.id = cudaLaunchAttributeProgrammaticStreamSerialization;
    pdl_attr.val.programmaticStreamSerializationAllowed = 1;

    {
        cudaLaunchConfig_t cfg = {};
        cfg.gridDim  = dim3((N_EDGES / 4 + 255) / 256);   // 3125
        cfg.blockDim = dim3(256);
        cfg.attrs    = &pdl_attr;
        cfg.numAttrs = 1;
        cudaLaunchKernelEx(&cfg, edge_exp_kernel, row, col, out);
    }
    {
        cudaLaunchConfig_t cfg = {};
        cfg.gridDim  = dim3((N_EDGES / 2 + 255) / 256);   // 6250
        cfg.blockDim = dim3(256);
        cfg.attrs    = &pdl_attr;
        cfg.numAttrs = 1;
        cudaLaunchKernelEx(&cfg, normalize_kernel, row, out);
    }
}

// round 12
// speedup vs baseline: 1.0525x; 1.0087x over previous
#include <cuda_runtime.h>

#define N_NODES 100000
#define N_EDGES 3200000
#define C_DIM   256
#define NEG_SLOPE 0.2f

// Scratch (allocation-free): node score arrays + softmax denominator.
__device__ float g_s_src[N_NODES];
__device__ float g_s_dst[N_NODES];
__device__ float g_denom[N_NODES];

// ---------------------------------------------------------------------------
// Kernel 1 (FROZEN at measured-best R7 config, ~20.0us @ 66% DRAM ceiling):
// per-node scores s_src = x·att[:C], s_dst = x·att[C:], zero denom.
// One-shot, 2 nodes/warp, 4 front-batched LDG.128, float2 stores.
// ---------------------------------------------------------------------------
__global__ void __launch_bounds__(256)
node_scores_kernel(const float* __restrict__ x, const float* __restrict__ att) {
    const int gtid  = blockIdx.x * blockDim.x + threadIdx.x;
    const int warp  = gtid >> 5;            // 0 .. 49999
    const int lane  = threadIdx.x & 31;
    const int nodeA = warp * 2;
    if (nodeA >= N_NODES) return;

    const float4* a0 = reinterpret_cast<const float4*>(att);          // att[:C]
    const float4* a1 = reinterpret_cast<const float4*>(att + C_DIM);  // att[C:]

    const float4* xr = reinterpret_cast<const float4*>(x + (size_t)nodeA * C_DIM);
    float4 xa0 = xr[lane];
    float4 xa1 = xr[lane + 32];
    float4 xb0 = xr[lane + 64];
    float4 xb1 = xr[lane + 96];

    float4 av0 = a0[lane],      bv0 = a1[lane];       // L1/L2-resident (2KB)
    float4 av1 = a0[lane + 32], bv1 = a1[lane + 32];

    float s0a = xa0.x*av0.x + xa0.y*av0.y + xa0.z*av0.z + xa0.w*av0.w
              + xa1.x*av1.x + xa1.y*av1.y + xa1.z*av1.z + xa1.w*av1.w;
    float s1a = xa0.x*bv0.x + xa0.y*bv0.y + xa0.z*bv0.z + xa0.w*bv0.w
              + xa1.x*bv1.x + xa1.y*bv1.y + xa1.z*bv1.z + xa1.w*bv1.w;
    float s0b = xb0.x*av0.x + xb0.y*av0.y + xb0.z*av0.z + xb0.w*av0.w
              + xb1.x*av1.x + xb1.y*av1.y + xb1.z*av1.z + xb1.w*av1.w;
    float s1b = xb0.x*bv0.x + xb0.y*bv0.y + xb0.z*bv0.z + xb0.w*bv0.w
              + xb1.x*bv1.x + xb1.y*bv1.y + xb1.z*bv1.z + xb1.w*bv1.w;

#pragma unroll
    for (int off = 16; off; off >>= 1) {   // 4 independent reduce chains
        s0a += __shfl_down_sync(0xffffffffu, s0a, off);
        s1a += __shfl_down_sync(0xffffffffu, s1a, off);
        s0b += __shfl_down_sync(0xffffffffu, s0b, off);
        s1b += __shfl_down_sync(0xffffffffu, s1b, off);
    }
    if (lane == 0) {   // coalesced pair stores (nodeA even -> 8B aligned)
        *reinterpret_cast<float2*>(&g_s_src[nodeA]) = make_float2(s0a, s0b);
        *reinterpret_cast<float2*>(&g_s_dst[nodeA]) = make_float2(s1a, s1b);
        *reinterpret_cast<float2*>(&g_denom[nodeA]) = make_float2(0.f, 0.f);
    }
}

// ---------------------------------------------------------------------------
// Kernel 2 (config FROZEN: 4 edges/thread, 3125 blocks). PDL gap-removal
// ONLY: cudaGridDependencySynchronize() is the FIRST statement — no pre-sync
// memory traffic, so node_scores (DRAM-bound) loses zero bandwidth. R11
// showed pre-sync index loads here steal DRAM and regress the predecessor.
// Max-shift dropped (mathematically identical; |a|<=~8, fp32-safe).
// ---------------------------------------------------------------------------
__global__ void __launch_bounds__(256)
edge_exp_kernel(const int* __restrict__ row,
                const int* __restrict__ col,
                float* __restrict__ out) {
    cudaGridDependencySynchronize();   // first thing: no resource steal

    int i = blockIdx.x * blockDim.x + threadIdx.x;   // quad index
    if (i * 4 >= N_EDGES) return;

    int4 r4 = reinterpret_cast<const int4*>(row)[i];            // keep in L2
    int4 c4 = __ldcs(&reinterpret_cast<const int4*>(col)[i]);   // read-once

    // 8 independent scattered gathers in flight
    float ss0 = g_s_src[r4.x], ss1 = g_s_src[r4.y];
    float ss2 = g_s_src[r4.z], ss3 = g_s_src[r4.w];
    float sd0 = g_s_dst[c4.x], sd1 = g_s_dst[c4.y];
    float sd2 = g_s_dst[c4.z], sd3 = g_s_dst[c4.w];

    float a0 = ss0 + sd0, a1 = ss1 + sd1, a2 = ss2 + sd2, a3 = ss3 + sd3;
    a0 = a0 > 0.f ? a0 : NEG_SLOPE * a0;
    a1 = a1 > 0.f ? a1 : NEG_SLOPE * a1;
    a2 = a2 > 0.f ? a2 : NEG_SLOPE * a2;
    a3 = a3 > 0.f ? a3 : NEG_SLOPE * a3;
    float e0 = __expf(a0), e1 = __expf(a1), e2 = __expf(a2), e3 = __expf(a3);

    reinterpret_cast<float4*>(out)[i] = make_float4(e0, e1, e2, e3);

    atomicAdd(&g_denom[r4.x], e0);
    atomicAdd(&g_denom[r4.y], e1);
    atomicAdd(&g_denom[r4.z], e2);
    atomicAdd(&g_denom[r4.w], e3);
}

// ---------------------------------------------------------------------------
// Kernel 3 (config FROZEN: 2 edges/thread, 6250 blocks). PDL with pre-sync
// row load: edge_exp is latency-bound (not DRAM-bound) and this read is an
// L2 hit, so the overlap is free — the asymmetric case where pre-sync work
// pays. __fdividef (2^-21, tol 1e-3).
// ---------------------------------------------------------------------------
__global__ void __launch_bounds__(256)
normalize_kernel(const int* __restrict__ row, float* __restrict__ out) {
    int i = blockIdx.x * blockDim.x + threadIdx.x;   // pair index
    if (i * 2 >= N_EDGES) {
        cudaGridDependencySynchronize();
        return;
    }

    int2 r2 = reinterpret_cast<const int2*>(row)[i];   // pre-sync, L2 hit

    cudaGridDependencySynchronize();   // e values + denom now complete

    float d0 = g_denom[r2.x];
    float d1 = g_denom[r2.y];

    float2 v = reinterpret_cast<float2*>(out)[i];
    v.x = __fdividef(v.x, d0);
    v.y = __fdividef(v.y, d1);
    reinterpret_cast<float2*>(out)[i] = v;
}

// ---------------------------------------------------------------------------
extern "C" void kernel_launch(void* const* d_in, const int* in_sizes, int n_in,
                              void* d_out, int out_size) {
    const float* x    = (const float*)d_in[0];   // (N, C) f32
    const float* att  = (const float*)d_in[1];   // (2C, 1) f32
    const int*   edge = (const int*)d_in[2];     // (2, E) int32
    float*       out  = (float*)d_out;           // (1, E) f32

    const int* row = edge;             // edge_index[0]
    const int* col = edge + N_EDGES;   // edge_index[1]

    {   // one-shot, 2 nodes per warp: 50000 warps = 6250 blocks
        node_scores_kernel<<<6250, 256>>>(x, att);
    }

    cudaLaunchAttribute pdl_attr;
    pdl_attr.id = cudaLaunchAttributeProgrammaticStreamSerialization;
    pdl_attr.val.programmaticStreamSerializationAllowed = 1;

    {
        cudaLaunchConfig_t cfg = {};
        cfg.gridDim  = dim3((N_EDGES / 4 + 255) / 256);   // 3125
        cfg.blockDim = dim3(256);
        cfg.attrs    = &pdl_attr;
        cfg.numAttrs = 1;
        cudaLaunchKernelEx(&cfg, edge_exp_kernel, row, col, out);
    }
    {
        cudaLaunchConfig_t cfg = {};
        cfg.gridDim  = dim3((N_EDGES / 2 + 255) / 256);   // 6250
        cfg.blockDim = dim3(256);
        cfg.attrs    = &pdl_attr;
        cfg.numAttrs = 1;
        cudaLaunchKernelEx(&cfg, normalize_kernel, row, out);
    }
}